// round 16
// baseline (speedup 1.0000x reference)
#include <cuda_runtime.h>

// y[b,j0,j1,j2] = sum_{a1,a2,a3} x[b,a1,a2,a3] w0[a1,j0] w1[a2,j1] w2[a3,j2]
// Three identical in-smem stages per batch cube:
//   out[m*32+j] = sum_i in[i*1024+m] * w[i*32+j]
//
// F=4 fibers per thread (256 threads), m = t + 256*f.
// Each LDS.128 weight-quad broadcast feeds 4 fibers -> weight smem
// wavefronts (the measured R3 bottleneck, L1=82.6%) drop 4x.
// Global phys swizzle phys(L) = L ^ ((L>>5)&31): all access patterns
// (fiber reads, row writes, float4 epilogue) verified conflict-free.

#define NTHREADS 256
#define F 4
#define CUBE 32768   // 32*32*32 floats per batch element

typedef unsigned long long ull;

__device__ __forceinline__ ull pack2f(float a, float b) {
    ull r;
    asm("mov.b64 %0, {%1, %2};" : "=l"(r) : "f"(a), "f"(b));
    return r;
}
__device__ __forceinline__ void unpack2f(ull v, float &a, float &b) {
    asm("mov.b64 {%0, %1}, %2;" : "=f"(a), "=f"(b) : "l"(v));
}
// Packed fp32x2 FMA (sm_100+): two exact fp32 FMAs per instruction.
__device__ __forceinline__ ull fma2(ull a, ull b, ull c) {
    ull d;
    asm("fma.rn.f32x2 %0, %1, %2, %3;" : "=l"(d) : "l"(a), "l"(b), "l"(c));
    return d;
}

extern __shared__ float s_cube[];   // [32768] cube, then ull wp[3*512] packed weights

__global__ __launch_bounds__(NTHREADS, 1)
void L1_kernel(const float* __restrict__ x,
               const float* __restrict__ w0,
               const float* __restrict__ w1,
               const float* __restrict__ w2,
               float* __restrict__ out)
{
    float* cube = s_cube;
    ull* wp = reinterpret_cast<ull*>(s_cube + CUBE);

    const int t = threadIdx.x;
    const int b = blockIdx.x;

    // ---- pack weights: wp[stage*512 + j*16 + i2] = {w[2*i2][j], w[2*i2+1][j]}
    {
        const float* ws[3] = {w0, w1, w2};
        #pragma unroll
        for (int e = t; e < 1536; e += NTHREADS) {
            int stage = e >> 9;
            int r     = e & 511;
            int j     = r >> 4;
            int i2    = r & 15;
            const float* w = ws[stage];
            wp[e] = pack2f(w[(2 * i2) * 32 + j], w[(2 * i2 + 1) * 32 + j]);
        }
    }

    // Per-thread swizzle constants. phys(L) = (L & ~31) | ((L&31) ^ ((L>>5)&31))
    const int lane5 = t & 31;
    const int hig   = t >> 5;            // 0..7
    int rbase[F];                        // phys base for fiber reads (+ i*1024)
    int wbase[F];                        // logical base for row writes
    #pragma unroll
    for (int f = 0; f < F; f++) {
        int keyf = (8 * f + hig) & 31;   // ((m>>5)&31), m = t + 256f
        rbase[f] = 256 * f + (hig << 5) + (lane5 ^ keyf);
        wbase[f] = (t + 256 * f) * 32;
    }

    ull v[16 * F];

    // ================= stage 1: fibers straight from gmem =================
    {
        const float* xg = x + (size_t)b * CUBE;
        #pragma unroll
        for (int f = 0; f < F; f++) {
            #pragma unroll
            for (int i2 = 0; i2 < 16; i2++) {
                float a = xg[(2 * i2)     * 1024 + t + 256 * f];
                float c = xg[(2 * i2 + 1) * 1024 + t + 256 * f];
                v[f * 16 + i2] = pack2f(a, c);
            }
        }
        __syncthreads();   // wp ready
        #pragma unroll
        for (int j = 0; j < 32; j++) {
            const ulonglong2* wj = reinterpret_cast<const ulonglong2*>(wp + j * 16);
            ull acc0 = 0ull, acc1 = 0ull, acc2 = 0ull, acc3 = 0ull;
            #pragma unroll
            for (int q = 0; q < 8; q++) {
                ulonglong2 wv = wj[q];               // LDS.128 broadcast, feeds 4 fibers
                acc0 = fma2(v[ 0 + 2*q], wv.x, acc0);
                acc0 = fma2(v[ 0 + 2*q + 1], wv.y, acc0);
                acc1 = fma2(v[16 + 2*q], wv.x, acc1);
                acc1 = fma2(v[16 + 2*q + 1], wv.y, acc1);
                acc2 = fma2(v[32 + 2*q], wv.x, acc2);
                acc2 = fma2(v[32 + 2*q + 1], wv.y, acc2);
                acc3 = fma2(v[48 + 2*q], wv.x, acc3);
                acc3 = fma2(v[48 + 2*q + 1], wv.y, acc3);
            }
            float lo, hh;
            unpack2f(acc0, lo, hh); cube[wbase[0] + (j ^ lane5)] = lo + hh;
            unpack2f(acc1, lo, hh); cube[wbase[1] + (j ^ lane5)] = lo + hh;
            unpack2f(acc2, lo, hh); cube[wbase[2] + (j ^ lane5)] = lo + hh;
            unpack2f(acc3, lo, hh); cube[wbase[3] + (j ^ lane5)] = lo + hh;
        }
    }

    // ================= stages 2 and 3: in-place in smem =================
    #pragma unroll
    for (int stage = 1; stage < 3; stage++) {
        __syncthreads();   // previous stage's writes visible
        #pragma unroll
        for (int f = 0; f < F; f++) {
            #pragma unroll
            for (int i2 = 0; i2 < 16; i2++) {
                float a = cube[(2 * i2)     * 1024 + rbase[f]];
                float c = cube[(2 * i2 + 1) * 1024 + rbase[f]];
                v[f * 16 + i2] = pack2f(a, c);
            }
        }
        __syncthreads();   // all fiber reads done before any in-place write
        const ull* wk = wp + stage * 512;
        #pragma unroll
        for (int j = 0; j < 32; j++) {
            const ulonglong2* wj = reinterpret_cast<const ulonglong2*>(wk + j * 16);
            ull acc0 = 0ull, acc1 = 0ull, acc2 = 0ull, acc3 = 0ull;
            #pragma unroll
            for (int q = 0; q < 8; q++) {
                ulonglong2 wv = wj[q];
                acc0 = fma2(v[ 0 + 2*q], wv.x, acc0);
                acc0 = fma2(v[ 0 + 2*q + 1], wv.y, acc0);
                acc1 = fma2(v[16 + 2*q], wv.x, acc1);
                acc1 = fma2(v[16 + 2*q + 1], wv.y, acc1);
                acc2 = fma2(v[32 + 2*q], wv.x, acc2);
                acc2 = fma2(v[32 + 2*q + 1], wv.y, acc2);
                acc3 = fma2(v[48 + 2*q], wv.x, acc3);
                acc3 = fma2(v[48 + 2*q + 1], wv.y, acc3);
            }
            float lo, hh;
            unpack2f(acc0, lo, hh); cube[wbase[0] + (j ^ lane5)] = lo + hh;
            unpack2f(acc1, lo, hh); cube[wbase[1] + (j ^ lane5)] = lo + hh;
            unpack2f(acc2, lo, hh); cube[wbase[2] + (j ^ lane5)] = lo + hh;
            unpack2f(acc3, lo, hh); cube[wbase[3] + (j ^ lane5)] = lo + hh;
        }
    }
    __syncthreads();

    // ================= smem -> gmem, coalesced float4 =================
    float* og = out + (size_t)b * CUBE;
    const int ekey = (t >> 3) & 31;      // ((L>>5)&31) for L = k*1024 + 4t
    #pragma unroll
    for (int k = 0; k < 32; k++) {
        int L = k * 1024 + t * 4;
        float4 r;
        r.x = cube[(L + 0) ^ ekey];
        r.y = cube[(L + 1) ^ ekey];
        r.z = cube[(L + 2) ^ ekey];
        r.w = cube[(L + 3) ^ ekey];
        *reinterpret_cast<float4*>(og + L) = r;
    }
}

extern "C" void kernel_launch(void* const* d_in, const int* in_sizes, int n_in,
                              void* d_out, int out_size) {
    const float* x  = (const float*)d_in[0];
    const float* w0 = (const float*)d_in[1];
    const float* w1 = (const float*)d_in[2];
    const float* w2 = (const float*)d_in[3];
    float* out = (float*)d_out;

    int batch = in_sizes[0] / CUBE;   // 1024 for the given shapes

    size_t smem = CUBE * sizeof(float) + 3 * 512 * sizeof(ull); // 143360 B
    cudaFuncSetAttribute(L1_kernel, cudaFuncAttributeMaxDynamicSharedMemorySize, (int)smem);

    L1_kernel<<<batch, NTHREADS, smem>>>(x, w0, w1, w2, out);
}